// round 6
// baseline (speedup 1.0000x reference)
#include <cuda_runtime.h>
#include <math.h>

#define EPSBN 1e-5f

typedef unsigned long long u64;

// ---------------- device scratch (no allocations allowed) ----------------
__device__ float g_h1[64 * 32 * 112 * 112];   // 102.8 MB
__device__ float g_h2[64 * 64 * 112 * 112];   // 205.5 MB
__device__ float g_h3[64 * 128 * 56 * 56];    // 102.8 MB
__device__ float g_pool[64 * 128];
__device__ float g_qtmp[128 * 64 * 9];        // largest OIHW ternarized weight (w3)
__device__ float g_qwl[10 * 128];
__device__ float g_w1r[9 * 3 * 32];           // [tap][ic][oc]
__device__ float g_w2r[9 * 32 * 64];
__device__ float g_w3r[9 * 64 * 128];

// ---------------- packed fp32x2 helpers (sm_103a) ----------------
__device__ __forceinline__ u64 pack2(float x) {
    u64 d; unsigned u = __float_as_uint(x);
    asm("mov.b64 %0, {%1, %1};" : "=l"(d) : "r"(u));
    return d;
}
__device__ __forceinline__ void fma2(u64& d, u64 a, u64 b) {
    asm("fma.rn.f32x2 %0, %1, %2, %0;" : "+l"(d) : "l"(a), "l"(b));
}
__device__ __forceinline__ float lo2(u64 v) { return __uint_as_float((unsigned)v); }
__device__ __forceinline__ float hi2(u64 v) { return __uint_as_float((unsigned)(v >> 32)); }

// ---------------- ternarize (TWN) ----------------
// delta = 0.7*mean|w|; alpha = mean|w| over entries above delta; q = alpha*sign(w)*mask
__global__ void ternarize_kernel(const float* __restrict__ w, int n, int dst) {
    __shared__ double reda[256];
    __shared__ double redc[256];
    __shared__ float s_delta, s_alpha;
    float* q = dst ? g_qwl : g_qtmp;
    int tid = threadIdx.x;

    double s = 0.0;
    for (int i = tid; i < n; i += 256) s += (double)fabsf(w[i]);
    reda[tid] = s; __syncthreads();
    for (int off = 128; off > 0; off >>= 1) {
        if (tid < off) reda[tid] += reda[tid + off];
        __syncthreads();
    }
    if (tid == 0) s_delta = (float)(0.7 * reda[0] / (double)n);
    __syncthreads();
    float delta = s_delta;

    double sa = 0.0, cnt = 0.0;
    for (int i = tid; i < n; i += 256) {
        float a = fabsf(w[i]);
        if (a > delta) { sa += (double)a; cnt += 1.0; }
    }
    reda[tid] = sa; redc[tid] = cnt; __syncthreads();
    for (int off = 128; off > 0; off >>= 1) {
        if (tid < off) { reda[tid] += reda[tid + off]; redc[tid] += redc[tid + off]; }
        __syncthreads();
    }
    if (tid == 0) s_alpha = (float)(reda[0] / fmax(redc[0], 1.0));
    __syncthreads();
    float alpha = s_alpha;

    for (int i = tid; i < n; i += 256) {
        float wv = w[i];
        q[i] = (fabsf(wv) > delta) ? copysignf(alpha, wv) : 0.0f;
    }
}

// repack OIHW -> [tap][ic][oc]
__global__ void repack_kernel(int IC, int OC, int which) {
    float* out = (which == 0) ? g_w1r : (which == 1) ? g_w2r : g_w3r;
    int total = 9 * IC * OC;
    for (int idx = blockIdx.x * blockDim.x + threadIdx.x; idx < total;
         idx += gridDim.x * blockDim.x) {
        int oc = idx % OC;
        int t = idx / OC;
        int ic = t % IC;
        int r = t / IC;
        out[idx] = g_qtmp[(oc * IC + ic) * 9 + r];
    }
}

// ---------------- conv1: [64,3,224,224] -> [64,32,112,112], s2 p1, BN+ReLU ----------------
__global__ __launch_bounds__(256) void conv1_kernel(
    const float* __restrict__ x, const float* __restrict__ g, const float* __restrict__ b,
    const float* __restrict__ m, const float* __restrict__ v) {
    __shared__ __align__(16) float sX[3 * 33 * 33];
    __shared__ __align__(16) float sW[9 * 3 * 32];   // 16B-aligned: read via float4 (LDS.128)
    __shared__ float sBNi[32], sBNa[32];

    int tid = threadIdx.x;
    int n = blockIdx.z;
    int ty0 = blockIdx.y * 16, tx0 = blockIdx.x * 16;
    int iy0 = 2 * ty0 - 1, ix0 = 2 * tx0 - 1;

    for (int i = tid; i < 3 * 33 * 33; i += 256) {
        int lx = i % 33; int t = i / 33; int ly = t % 33; int ic = t / 33;
        int gy = iy0 + ly, gx = ix0 + lx;
        float val = 0.f;
        if (gy >= 0 && gy < 224 && gx >= 0 && gx < 224)
            val = x[((n * 3 + ic) * 224 + gy) * 224 + gx];
        sX[i] = val;
    }
    for (int i = tid; i < 9 * 3 * 32; i += 256) sW[i] = g_w1r[i];
    if (tid < 32) {
        float inv = g[tid] / sqrtf(v[tid] + EPSBN);
        sBNi[tid] = inv; sBNa[tid] = b[tid] - m[tid] * inv;
    }
    __syncthreads();

    int py = tid / 16, px = tid % 16;
    float acc[32];
#pragma unroll
    for (int k = 0; k < 32; ++k) acc[k] = 0.f;

    for (int ic = 0; ic < 3; ++ic) {
#pragma unroll
        for (int r = 0; r < 9; ++r) {
            float xv = sX[ic * 1089 + (2 * py + r / 3) * 33 + (2 * px + r % 3)];
            const float4* w4 = (const float4*)&sW[(r * 3 + ic) * 32];
#pragma unroll
            for (int j = 0; j < 8; ++j) {
                float4 w = w4[j];
                acc[4 * j + 0] += xv * w.x;
                acc[4 * j + 1] += xv * w.y;
                acc[4 * j + 2] += xv * w.z;
                acc[4 * j + 3] += xv * w.w;
            }
        }
    }

    int oy = ty0 + py, ox = tx0 + px;
    int base = (n * 32) * 12544 + oy * 112 + ox;
#pragma unroll
    for (int oc = 0; oc < 32; ++oc) {
        float val = fmaxf(acc[oc] * sBNi[oc] + sBNa[oc], 0.f);
        g_h1[base + oc * 12544] = val;
    }
}

// ---------------- conv2: [64,32,112,112] -> [64,64,112,112], s1 p1, BN+ReLU ----------------
// 512 threads: 256 pixels (16x16 tile) x 2 oc-halves of 32. fp32x2 accumulators.
__global__ __launch_bounds__(512) void conv2_kernel(
    const float* __restrict__ g, const float* __restrict__ b,
    const float* __restrict__ m, const float* __restrict__ v) {
    extern __shared__ __align__(16) float smem[];
    float* sX = smem;              // 32*18*18 = 10368 floats (41472 B, 16B-mult)
    float* sW = smem + 10368;      // 9*32*64 = 18432 floats
    __shared__ float sBNi[64], sBNa[64];

    int tid = threadIdx.x;
    int n = blockIdx.z;
    int ty0 = blockIdx.y * 16, tx0 = blockIdx.x * 16;

    for (int i = tid; i < 10368; i += 512) {
        int lx = i % 18; int t = i / 18; int ly = t % 18; int ic = t / 18;
        int gy = ty0 - 1 + ly, gx = tx0 - 1 + lx;
        float val = 0.f;
        if (gy >= 0 && gy < 112 && gx >= 0 && gx < 112)
            val = g_h1[((n * 32 + ic) * 112 + gy) * 112 + gx];
        sX[i] = val;
    }
    for (int i = tid; i < 18432; i += 512) sW[i] = g_w2r[i];
    if (tid < 64) {
        float inv = g[tid] / sqrtf(v[tid] + EPSBN);
        sBNi[tid] = inv; sBNa[tid] = b[tid] - m[tid] * inv;
    }
    __syncthreads();

    int half = tid >> 8;
    int p = tid & 255;
    int py = p >> 4, px = p & 15;
    int ocb = half * 32;

    u64 acc[16];
#pragma unroll
    for (int k = 0; k < 16; ++k) acc[k] = 0ull;

    for (int ic = 0; ic < 32; ++ic) {
#pragma unroll
        for (int r = 0; r < 9; ++r) {
            u64 xv2 = pack2(sX[ic * 324 + (py + r / 3) * 18 + (px + r % 3)]);
            const ulonglong2* w2 = (const ulonglong2*)&sW[(r * 32 + ic) * 64 + ocb];
#pragma unroll
            for (int j = 0; j < 8; ++j) {
                ulonglong2 ww = w2[j];
                fma2(acc[2 * j + 0], xv2, ww.x);
                fma2(acc[2 * j + 1], xv2, ww.y);
            }
        }
    }

    int oy = ty0 + py, ox = tx0 + px;
    int base = ((n * 64 + ocb) * 112 + oy) * 112 + ox;
#pragma unroll
    for (int k = 0; k < 16; ++k) {
        float v0 = lo2(acc[k]), v1 = hi2(acc[k]);
        int oc0 = ocb + 2 * k;
        g_h2[base + (2 * k + 0) * 12544] = fmaxf(v0 * sBNi[oc0] + sBNa[oc0], 0.f);
        g_h2[base + (2 * k + 1) * 12544] = fmaxf(v1 * sBNi[oc0 + 1] + sBNa[oc0 + 1], 0.f);
    }
}

// ---------------- conv3: [64,64,112,112] -> [64,128,56,56], s2 p1, BN+ReLU ----------------
// 448 threads: 224 pixels (8x28 tile) x 2 oc-halves of 64. IC chunked by 16 (4 chunks).
__global__ __launch_bounds__(448) void conv3_kernel(
    const float* __restrict__ g, const float* __restrict__ b,
    const float* __restrict__ m, const float* __restrict__ v) {
    extern __shared__ __align__(16) float smem[];
    float* sX = smem;              // 16*17*57 = 15504 floats (62016 B, 16B-mult)
    float* sW = smem + 15504;      // 9*16*128 = 18432 floats
    __shared__ float sBNi[128], sBNa[128];

    int tid = threadIdx.x;
    int n = blockIdx.z;
    int ty0 = blockIdx.y * 8, tx0 = blockIdx.x * 28;
    int iy0 = 2 * ty0 - 1, ix0 = 2 * tx0 - 1;

    if (tid < 128) {
        float inv = g[tid] / sqrtf(v[tid] + EPSBN);
        sBNi[tid] = inv; sBNa[tid] = b[tid] - m[tid] * inv;
    }

    int half = tid / 224;
    int p = tid % 224;
    int py = p / 28, px = p % 28;
    int ocb = half * 64;

    u64 acc[32];
#pragma unroll
    for (int k = 0; k < 32; ++k) acc[k] = 0ull;

    for (int chunk = 0; chunk < 4; ++chunk) {
        __syncthreads();
        for (int i = tid; i < 15504; i += 448) {
            int lx = i % 57; int t = i / 57; int ly = t % 17; int icl = t / 17;
            int ic = chunk * 16 + icl;
            int gy = iy0 + ly, gx = ix0 + lx;
            float val = 0.f;
            if (gy >= 0 && gy < 112 && gx >= 0 && gx < 112)
                val = g_h2[((n * 64 + ic) * 112 + gy) * 112 + gx];
            sX[i] = val;
        }
        for (int i = tid; i < 18432; i += 448) {
            int oc = i % 128; int t = i / 128; int icl = t % 16; int r = t / 16;
            sW[i] = g_w3r[(r * 64 + chunk * 16 + icl) * 128 + oc];
        }
        __syncthreads();

        for (int icl = 0; icl < 16; ++icl) {
#pragma unroll
            for (int r = 0; r < 9; ++r) {
                u64 xv2 = pack2(sX[icl * 969 + (2 * py + r / 3) * 57 + (2 * px + r % 3)]);
                const ulonglong2* w2 = (const ulonglong2*)&sW[(r * 16 + icl) * 128 + ocb];
#pragma unroll
                for (int j = 0; j < 16; ++j) {
                    ulonglong2 ww = w2[j];
                    fma2(acc[2 * j + 0], xv2, ww.x);
                    fma2(acc[2 * j + 1], xv2, ww.y);
                }
            }
        }
    }

    int oy = ty0 + py, ox = tx0 + px;
    int base = ((n * 128 + ocb) * 56 + oy) * 56 + ox;
#pragma unroll
    for (int k = 0; k < 32; ++k) {
        float v0 = lo2(acc[k]), v1 = hi2(acc[k]);
        int oc0 = ocb + 2 * k;
        g_h3[base + (2 * k + 0) * 3136] = fmaxf(v0 * sBNi[oc0] + sBNa[oc0], 0.f);
        g_h3[base + (2 * k + 1) * 3136] = fmaxf(v1 * sBNi[oc0 + 1] + sBNa[oc0 + 1], 0.f);
    }
}

// ---------------- global average pool: h3 -> pool (sum, /3136 folded into final) ----------------
__global__ void pool_kernel() {
    int c = blockIdx.x;  // n*128 + oc, 8192 blocks
    const float* src = g_h3 + (long)c * 3136;
    float s = 0.f;
    for (int i = threadIdx.x; i < 3136; i += 128) s += src[i];
    __shared__ float red[4];
#pragma unroll
    for (int o = 16; o > 0; o >>= 1) s += __shfl_xor_sync(0xffffffff, s, o);
    if ((threadIdx.x & 31) == 0) red[threadIdx.x >> 5] = s;
    __syncthreads();
    if (threadIdx.x == 0) g_pool[c] = red[0] + red[1] + red[2] + red[3];
}

// ---------------- final linear: out[n,c] = mean(h3) @ qwl.T + bl ----------------
__global__ void final_kernel(const float* __restrict__ bl, float* __restrict__ out) {
    int tid = blockIdx.x * blockDim.x + threadIdx.x;
    if (tid >= 640) return;
    int n = tid / 10, c = tid % 10;
    const float* p = g_pool + n * 128;
    const float* w = g_qwl + c * 128;
    float s = 0.f;
#pragma unroll 8
    for (int k = 0; k < 128; ++k) s += p[k] * w[k];
    out[tid] = s * (1.0f / 3136.0f) + bl[c];
}

// ---------------- launch ----------------
extern "C" void kernel_launch(void* const* d_in, const int* in_sizes, int n_in,
                              void* d_out, int out_size) {
    const float* x  = (const float*)d_in[0];
    const float* w1 = (const float*)d_in[1];
    const float* g1 = (const float*)d_in[2];
    const float* b1 = (const float*)d_in[3];
    const float* m1 = (const float*)d_in[4];
    const float* v1 = (const float*)d_in[5];
    const float* w2 = (const float*)d_in[6];
    const float* g2 = (const float*)d_in[7];
    const float* b2 = (const float*)d_in[8];
    const float* m2 = (const float*)d_in[9];
    const float* v2 = (const float*)d_in[10];
    const float* w3 = (const float*)d_in[11];
    const float* g3 = (const float*)d_in[12];
    const float* b3 = (const float*)d_in[13];
    const float* m3 = (const float*)d_in[14];
    const float* v3 = (const float*)d_in[15];
    const float* wl = (const float*)d_in[16];
    const float* bl = (const float*)d_in[17];
    float* out = (float*)d_out;

    cudaFuncSetAttribute((const void*)conv2_kernel,
                         cudaFuncAttributeMaxDynamicSharedMemorySize, 115200);
    cudaFuncSetAttribute((const void*)conv3_kernel,
                         cudaFuncAttributeMaxDynamicSharedMemorySize, 135744);

    // ternarize + repack weights
    ternarize_kernel<<<1, 256>>>(w1, 32 * 3 * 9, 0);
    repack_kernel<<<16, 256>>>(3, 32, 0);
    ternarize_kernel<<<1, 256>>>(w2, 64 * 32 * 9, 0);
    repack_kernel<<<72, 256>>>(32, 64, 1);
    ternarize_kernel<<<1, 256>>>(w3, 128 * 64 * 9, 0);
    repack_kernel<<<288, 256>>>(64, 128, 2);
    ternarize_kernel<<<1, 256>>>(wl, 10 * 128, 1);

    // layers
    conv1_kernel<<<dim3(7, 7, 64), 256>>>(x, g1, b1, m1, v1);
    conv2_kernel<<<dim3(7, 7, 64), 512, 115200>>>(g2, b2, m2, v2);
    conv3_kernel<<<dim3(2, 7, 64), 448, 135744>>>(g3, b3, m3, v3);
    pool_kernel<<<8192, 128>>>();
    final_kernel<<<3, 256>>>(bl, out);
}

// round 7
// speedup vs baseline: 1.2936x; 1.2936x over previous
#include <cuda_runtime.h>
#include <math.h>

#define EPSBN 1e-5f

typedef unsigned long long u64;

// ---------------- device scratch (no allocations allowed) ----------------
__device__ float g_h1[64 * 32 * 112 * 112];   // 102.8 MB
__device__ float g_h2[64 * 64 * 112 * 112];   // 205.5 MB
__device__ float g_h3[64 * 128 * 56 * 56];    // 102.8 MB
__device__ float g_pool[64 * 128];
__device__ float g_qwl[10 * 128];
__device__ float g_w1r[9 * 3 * 32];           // [tap][ic][oc]
__device__ float g_w2r[9 * 32 * 64];
__device__ float g_w3r[9 * 64 * 128];

// ---------------- packed fp32x2 helpers (sm_103a) ----------------
__device__ __forceinline__ u64 pack2(float x) {
    u64 d; unsigned u = __float_as_uint(x);
    asm("mov.b64 %0, {%1, %1};" : "=l"(d) : "r"(u));
    return d;
}
__device__ __forceinline__ void fma2(u64& d, u64 a, u64 b) {
    asm("fma.rn.f32x2 %0, %1, %2, %0;" : "+l"(d) : "l"(a), "l"(b));
}
__device__ __forceinline__ float lo2(u64 v) { return __uint_as_float((unsigned)v); }
__device__ __forceinline__ float hi2(u64 v) { return __uint_as_float((unsigned)(v >> 32)); }

// ---------------- fused ternarize (TWN) + repack OIHW -> [tap][ic][oc] ----------------
// delta = 0.7*mean|w|; alpha = mean|w| over entries above delta; q = alpha*sign(w)*mask
__global__ __launch_bounds__(1024) void prep_kernel(const float* __restrict__ w,
                                                    int n, int IC, int OC, int which) {
    __shared__ double reda[1024];
    __shared__ double redc[1024];
    __shared__ float s_delta, s_alpha;
    int tid = threadIdx.x;

    double s = 0.0;
    for (int i = tid; i < n; i += 1024) s += (double)fabsf(w[i]);
    reda[tid] = s; __syncthreads();
    for (int off = 512; off > 0; off >>= 1) {
        if (tid < off) reda[tid] += reda[tid + off];
        __syncthreads();
    }
    if (tid == 0) s_delta = (float)(0.7 * reda[0] / (double)n);
    __syncthreads();
    float delta = s_delta;

    double sa = 0.0, cnt = 0.0;
    for (int i = tid; i < n; i += 1024) {
        float a = fabsf(w[i]);
        if (a > delta) { sa += (double)a; cnt += 1.0; }
    }
    reda[tid] = sa; redc[tid] = cnt; __syncthreads();
    for (int off = 512; off > 0; off >>= 1) {
        if (tid < off) { reda[tid] += reda[tid + off]; redc[tid] += redc[tid + off]; }
        __syncthreads();
    }
    if (tid == 0) s_alpha = (float)(reda[0] / fmax(redc[0], 1.0));
    __syncthreads();
    float alpha = s_alpha;

    float* out = (which == 0) ? g_w1r : (which == 1) ? g_w2r
               : (which == 2) ? g_w3r : g_qwl;
    for (int i = tid; i < n; i += 1024) {
        float wv = w[i];
        float qv = (fabsf(wv) > delta) ? copysignf(alpha, wv) : 0.0f;
        if (which < 3) {
            int r = i % 9; int t = i / 9; int ic = t % IC; int oc = t / IC;
            out[(r * IC + ic) * OC + oc] = qv;
        } else {
            out[i] = qv;
        }
    }
}

// ---------------- conv1: [64,3,224,224] -> [64,32,112,112], s2 p1, BN+ReLU ----------------
__global__ __launch_bounds__(256) void conv1_kernel(
    const float* __restrict__ x, const float* __restrict__ g, const float* __restrict__ b,
    const float* __restrict__ m, const float* __restrict__ v) {
    __shared__ __align__(16) float sX[3 * 33 * 33];
    __shared__ __align__(16) float sW[9 * 3 * 32];
    __shared__ float sBNi[32], sBNa[32];

    int tid = threadIdx.x;
    int n = blockIdx.z;
    int ty0 = blockIdx.y * 16, tx0 = blockIdx.x * 16;
    int iy0 = 2 * ty0 - 1, ix0 = 2 * tx0 - 1;

    for (int i = tid; i < 3 * 33 * 33; i += 256) {
        int lx = i % 33; int t = i / 33; int ly = t % 33; int ic = t / 33;
        int gy = iy0 + ly, gx = ix0 + lx;
        float val = 0.f;
        if (gy >= 0 && gy < 224 && gx >= 0 && gx < 224)
            val = x[((n * 3 + ic) * 224 + gy) * 224 + gx];
        sX[i] = val;
    }
    for (int i = tid; i < 9 * 3 * 32; i += 256) sW[i] = g_w1r[i];
    if (tid < 32) {
        float inv = g[tid] / sqrtf(v[tid] + EPSBN);
        sBNi[tid] = inv; sBNa[tid] = b[tid] - m[tid] * inv;
    }
    __syncthreads();

    int py = tid / 16, px = tid % 16;
    float acc[32];
#pragma unroll
    for (int k = 0; k < 32; ++k) acc[k] = 0.f;

    for (int ic = 0; ic < 3; ++ic) {
#pragma unroll
        for (int r = 0; r < 9; ++r) {
            float xv = sX[ic * 1089 + (2 * py + r / 3) * 33 + (2 * px + r % 3)];
            const float4* w4 = (const float4*)&sW[(r * 3 + ic) * 32];
#pragma unroll
            for (int j = 0; j < 8; ++j) {
                float4 w = w4[j];
                acc[4 * j + 0] += xv * w.x;
                acc[4 * j + 1] += xv * w.y;
                acc[4 * j + 2] += xv * w.z;
                acc[4 * j + 3] += xv * w.w;
            }
        }
    }

    int oy = ty0 + py, ox = tx0 + px;
    int base = (n * 32) * 12544 + oy * 112 + ox;
#pragma unroll
    for (int oc = 0; oc < 32; ++oc) {
        float val = fmaxf(acc[oc] * sBNi[oc] + sBNa[oc], 0.f);
        g_h1[base + oc * 12544] = val;
    }
}

// ---------------- conv2: [64,32,112,112] -> [64,64,112,112], s1 p1, BN+ReLU ----------------
// 448 threads; tile 16x28 output pixels. Thread = 2 pixels (py, py+8) x 32 ocs.
// Per inner iter: 2 x-LDS + 8 weight LDS.128 (warp-uniform broadcast) feed 32 FFMA2.
__global__ __launch_bounds__(448) void conv2_kernel(
    const float* __restrict__ g, const float* __restrict__ b,
    const float* __restrict__ m, const float* __restrict__ v) {
    extern __shared__ __align__(16) float smem[];
    float* sX = smem;              // 32*18*30 = 17280 floats
    float* sW = smem + 17280;      // 9*32*64  = 18432 floats
    __shared__ float sBNi[64], sBNa[64];

    int tid = threadIdx.x;
    int n = blockIdx.z;
    int ty0 = blockIdx.y * 16, tx0 = blockIdx.x * 28;

    for (int i = tid; i < 17280; i += 448) {
        int lx = i % 30; int t = i / 30; int ly = t % 18; int ic = t / 18;
        int gy = ty0 - 1 + ly, gx = tx0 - 1 + lx;
        float val = 0.f;
        if (gy >= 0 && gy < 112 && gx >= 0 && gx < 112)
            val = g_h1[((n * 32 + ic) * 112 + gy) * 112 + gx];
        sX[i] = val;
    }
    for (int i = tid; i < 18432; i += 448) sW[i] = g_w2r[i];
    if (tid < 64) {
        float inv = g[tid] / sqrtf(v[tid] + EPSBN);
        sBNi[tid] = inv; sBNa[tid] = b[tid] - m[tid] * inv;
    }
    __syncthreads();

    int half = tid / 224;          // warp-aligned: 224 = 7 warps
    int p = tid % 224;
    int py = p / 28, px = p % 28;  // py 0..7; second pixel at py+8
    int ocb = half * 32;

    u64 acc0[16], acc1[16];
#pragma unroll
    for (int k = 0; k < 16; ++k) { acc0[k] = 0ull; acc1[k] = 0ull; }

    for (int ic = 0; ic < 32; ++ic) {
        const float* xb = &sX[ic * 540 + py * 30 + px];
        const float* wb = &sW[ic * 64 + ocb];
#pragma unroll
        for (int r = 0; r < 9; ++r) {
            int dy = r / 3, dx = r % 3;
            u64 x0 = pack2(xb[dy * 30 + dx]);
            u64 x1 = pack2(xb[(dy + 8) * 30 + dx]);
            const ulonglong2* wv = (const ulonglong2*)&wb[r * 2048];  // (r*32+ic)*64
#pragma unroll
            for (int j = 0; j < 8; ++j) {
                ulonglong2 ww = wv[j];
                fma2(acc0[2 * j + 0], x0, ww.x);
                fma2(acc0[2 * j + 1], x0, ww.y);
                fma2(acc1[2 * j + 0], x1, ww.x);
                fma2(acc1[2 * j + 1], x1, ww.y);
            }
        }
    }

    int oy = ty0 + py, ox = tx0 + px;
    long base = ((long)(n * 64 + ocb)) * 12544 + oy * 112 + ox;
#pragma unroll
    for (int k = 0; k < 16; ++k) {
        int oc0 = ocb + 2 * k;
        float i0 = sBNi[oc0], a0 = sBNa[oc0];
        float i1 = sBNi[oc0 + 1], a1 = sBNa[oc0 + 1];
        g_h2[base + (2 * k + 0) * 12544]           = fmaxf(lo2(acc0[k]) * i0 + a0, 0.f);
        g_h2[base + (2 * k + 1) * 12544]           = fmaxf(hi2(acc0[k]) * i1 + a1, 0.f);
        g_h2[base + (2 * k + 0) * 12544 + 8 * 112] = fmaxf(lo2(acc1[k]) * i0 + a0, 0.f);
        g_h2[base + (2 * k + 1) * 12544 + 8 * 112] = fmaxf(hi2(acc1[k]) * i1 + a1, 0.f);
    }
}

// ---------------- conv3: [64,64,112,112] -> [64,128,56,56], s2 p1, BN+ReLU ----------------
// 448 threads; tile 8x28 output pixels. Thread = 2 pixels (py, py+4) x 32 ocs (quarter).
// IC chunked by 16 (4 chunks), weights+x staged per chunk.
__global__ __launch_bounds__(448) void conv3_kernel(
    const float* __restrict__ g, const float* __restrict__ b,
    const float* __restrict__ m, const float* __restrict__ v) {
    extern __shared__ __align__(16) float smem[];
    float* sX = smem;              // 16*17*57 = 15504 floats
    float* sW = smem + 15504;      // 9*16*128 = 18432 floats
    __shared__ float sBNi[128], sBNa[128];

    int tid = threadIdx.x;
    int n = blockIdx.z;
    int ty0 = blockIdx.y * 8, tx0 = blockIdx.x * 28;
    int iy0 = 2 * ty0 - 1, ix0 = 2 * tx0 - 1;

    if (tid < 128) {
        float inv = g[tid] / sqrtf(v[tid] + EPSBN);
        sBNi[tid] = inv; sBNa[tid] = b[tid] - m[tid] * inv;
    }

    int q = tid / 112;             // oc quarter
    int pp = tid % 112;
    int py = pp / 28, px = pp % 28;  // py 0..3; second pixel at py+4
    int ocb = q * 32;

    u64 acc0[16], acc1[16];
#pragma unroll
    for (int k = 0; k < 16; ++k) { acc0[k] = 0ull; acc1[k] = 0ull; }

    for (int chunk = 0; chunk < 4; ++chunk) {
        __syncthreads();
        for (int i = tid; i < 15504; i += 448) {
            int lx = i % 57; int t = i / 57; int ly = t % 17; int icl = t / 17;
            int ic = chunk * 16 + icl;
            int gy = iy0 + ly, gx = ix0 + lx;
            float val = 0.f;
            if (gy >= 0 && gy < 112 && gx >= 0 && gx < 112)
                val = g_h2[((n * 64 + ic) * 112 + gy) * 112 + gx];
            sX[i] = val;
        }
        for (int i = tid; i < 18432; i += 448) {
            int oc = i % 128; int t = i / 128; int icl = t % 16; int r = t / 16;
            sW[i] = g_w3r[(r * 64 + chunk * 16 + icl) * 128 + oc];
        }
        __syncthreads();

        for (int icl = 0; icl < 16; ++icl) {
            const float* xb = &sX[icl * 969 + 2 * py * 57 + 2 * px];
            const float* wb = &sW[icl * 128 + ocb];
#pragma unroll
            for (int r = 0; r < 9; ++r) {
                int dy = r / 3, dx = r % 3;
                u64 x0 = pack2(xb[dy * 57 + dx]);
                u64 x1 = pack2(xb[(dy + 8) * 57 + dx]);   // pixel py+4 -> input +8 rows
                const ulonglong2* wv = (const ulonglong2*)&wb[r * 2048];  // (r*16+icl)*128
#pragma unroll
                for (int j = 0; j < 8; ++j) {
                    ulonglong2 ww = wv[j];
                    fma2(acc0[2 * j + 0], x0, ww.x);
                    fma2(acc0[2 * j + 1], x0, ww.y);
                    fma2(acc1[2 * j + 0], x1, ww.x);
                    fma2(acc1[2 * j + 1], x1, ww.y);
                }
            }
        }
    }

    int oy = ty0 + py, ox = tx0 + px;
    long base = ((long)(n * 128 + ocb)) * 3136 + oy * 56 + ox;
#pragma unroll
    for (int k = 0; k < 16; ++k) {
        int oc0 = ocb + 2 * k;
        float i0 = sBNi[oc0], a0 = sBNa[oc0];
        float i1 = sBNi[oc0 + 1], a1 = sBNa[oc0 + 1];
        g_h3[base + (2 * k + 0) * 3136]          = fmaxf(lo2(acc0[k]) * i0 + a0, 0.f);
        g_h3[base + (2 * k + 1) * 3136]          = fmaxf(hi2(acc0[k]) * i1 + a1, 0.f);
        g_h3[base + (2 * k + 0) * 3136 + 4 * 56] = fmaxf(lo2(acc1[k]) * i0 + a0, 0.f);
        g_h3[base + (2 * k + 1) * 3136 + 4 * 56] = fmaxf(hi2(acc1[k]) * i1 + a1, 0.f);
    }
}

// ---------------- global average pool: h3 -> pool (sum; /3136 folded into final) ----------------
__global__ void pool_kernel() {
    int c = blockIdx.x;  // n*128 + oc, 8192 blocks
    const float* src = g_h3 + (long)c * 3136;
    float s = 0.f;
    for (int i = threadIdx.x; i < 3136; i += 128) s += src[i];
    __shared__ float red[4];
#pragma unroll
    for (int o = 16; o > 0; o >>= 1) s += __shfl_xor_sync(0xffffffff, s, o);
    if ((threadIdx.x & 31) == 0) red[threadIdx.x >> 5] = s;
    __syncthreads();
    if (threadIdx.x == 0) g_pool[c] = red[0] + red[1] + red[2] + red[3];
}

// ---------------- final linear: out[n,c] = mean(h3) @ qwl.T + bl ----------------
__global__ void final_kernel(const float* __restrict__ bl, float* __restrict__ out) {
    int tid = blockIdx.x * blockDim.x + threadIdx.x;
    if (tid >= 640) return;
    int n = tid / 10, c = tid % 10;
    const float* p = g_pool + n * 128;
    const float* w = g_qwl + c * 128;
    float s = 0.f;
#pragma unroll 8
    for (int k = 0; k < 128; ++k) s += p[k] * w[k];
    out[tid] = s * (1.0f / 3136.0f) + bl[c];
}

// ---------------- launch ----------------
extern "C" void kernel_launch(void* const* d_in, const int* in_sizes, int n_in,
                              void* d_out, int out_size) {
    const float* x  = (const float*)d_in[0];
    const float* w1 = (const float*)d_in[1];
    const float* g1 = (const float*)d_in[2];
    const float* b1 = (const float*)d_in[3];
    const float* m1 = (const float*)d_in[4];
    const float* v1 = (const float*)d_in[5];
    const float* w2 = (const float*)d_in[6];
    const float* g2 = (const float*)d_in[7];
    const float* b2 = (const float*)d_in[8];
    const float* m2 = (const float*)d_in[9];
    const float* v2 = (const float*)d_in[10];
    const float* w3 = (const float*)d_in[11];
    const float* g3 = (const float*)d_in[12];
    const float* b3 = (const float*)d_in[13];
    const float* m3 = (const float*)d_in[14];
    const float* v3 = (const float*)d_in[15];
    const float* wl = (const float*)d_in[16];
    const float* bl = (const float*)d_in[17];
    float* out = (float*)d_out;

    cudaFuncSetAttribute((const void*)conv2_kernel,
                         cudaFuncAttributeMaxDynamicSharedMemorySize, 142848);
    cudaFuncSetAttribute((const void*)conv3_kernel,
                         cudaFuncAttributeMaxDynamicSharedMemorySize, 135744);

    // weight prep (4 launches -> launch index 5 == conv2 for ncu -s 5 -c 1)
    prep_kernel<<<1, 1024>>>(w1, 32 * 3 * 9, 3, 32, 0);
    prep_kernel<<<1, 1024>>>(w2, 64 * 32 * 9, 32, 64, 1);
    prep_kernel<<<1, 1024>>>(w3, 128 * 64 * 9, 64, 128, 2);
    prep_kernel<<<1, 1024>>>(wl, 10 * 128, 128, 10, 3);

    // layers
    conv1_kernel<<<dim3(7, 7, 64), 256>>>(x, g1, b1, m1, v1);
    conv2_kernel<<<dim3(4, 7, 64), 448, 142848>>>(g2, b2, m2, v2);
    conv3_kernel<<<dim3(2, 7, 64), 448, 135744>>>(g3, b3, m3, v3);
    pool_kernel<<<8192, 128>>>();
    final_kernel<<<3, 256>>>(bl, out);
}